// round 1
// baseline (speedup 1.0000x reference)
#include <cuda_runtime.h>
#include <math.h>
#include <stdint.h>

#define NN 50000
#define EE 800000
#define DD 128
#define BB 32
#define LL 3

// ---------------- scratch (static device globals; no allocation) ----------------
__device__ float g_h[NN * DD];        // node state
__device__ float g_hpre[NN * DD];     // pre-layernorm
__device__ float g_Z[NN * 384];       // [P | Q | T] per node
__device__ float g_Hacc[NN * DD];     // scatter accumulator
__device__ float g_tp[BB * DD];       // time projection
__device__ float g_dist[EE];
__device__ float g_deg[NN];
__device__ float g_invdeg[NN];
__device__ float g_Wk1[LL * DD * 384];  // packed [W1a | W1b | nw1]
__device__ float g_bk1[LL * 384];
__device__ float g_Wk3[LL * 256 * DD];  // packed [nw2 ; ew2]
__device__ float g_bk3[LL * DD];        // nb2 + eb2
__device__ int   g_is64;

__device__ __forceinline__ float silu_f(float x) { return x / (1.f + __expf(-x)); }

__device__ __forceinline__ long long idx_at(const void* p, long long i) {
    if (g_is64) return ((const long long*)p)[i];
    return (long long)((const int*)p)[i];
}

// ---------------- dtype detection for edge_index / batch -------------------------
// If int64, every high 32-bit word is 0 (values < 50000). If int32, the odd words
// are random edge indices; all-128-zero is impossible for random data.
__global__ void detect_idx_kernel(const unsigned* w) {
    int is64 = 1;
    for (int i = 1; i < 256; i += 2)
        if (w[i] != 0u) { is64 = 0; break; }
    g_is64 = is64;
}

// ---------------- weight packing -------------------------------------------------
__global__ void pack_w_kernel(const float* __restrict__ ew1, const float* __restrict__ eb1,
                              const float* __restrict__ ew2, const float* __restrict__ eb2,
                              const float* __restrict__ nw1, const float* __restrict__ nb1,
                              const float* __restrict__ nw2, const float* __restrict__ nb2) {
    int idx = blockIdx.x * blockDim.x + threadIdx.x;
    if (idx < LL * DD * 384) {
        int l = idx / (DD * 384);
        int rem = idx % (DD * 384);
        int k = rem / 384;
        int j = rem % 384;
        float v;
        if (j < 128)       v = ew1[l * 257 * 128 + k * 128 + j];
        else if (j < 256)  v = ew1[l * 257 * 128 + (128 + k) * 128 + (j - 128)];
        else               v = nw1[l * 128 * 128 + k * 128 + (j - 256)];
        g_Wk1[idx] = v;
    }
    if (idx < LL * 256 * DD) {
        int l = idx / (256 * DD);
        int rem = idx % (256 * DD);
        int k = rem / DD;
        int j = rem % DD;
        float v = (k < 128) ? nw2[l * 128 * 128 + k * 128 + j]
                            : ew2[l * 128 * 128 + (k - 128) * 128 + j];
        g_Wk3[idx] = v;
    }
    if (idx < LL * 384) {
        int l = idx / 384;
        int j = idx % 384;
        float v;
        if (j < 128)      v = eb1[l * 128 + j];
        else if (j < 256) v = 0.f;
        else              v = nb1[l * 128 + (j - 256)];
        g_bk1[idx] = v;
    }
    if (idx < LL * DD) {
        g_bk3[idx] = nb2[idx] + eb2[idx];
    }
}

// ---------------- time MLP: tp = silu(te@tw1+tb1)@tw2+tb2  (32x128) --------------
__global__ void time_mlp_kernel(const float* __restrict__ te,
                                const float* __restrict__ tw1, const float* __restrict__ tb1,
                                const float* __restrict__ tw2, const float* __restrict__ tb2) {
    __shared__ float row[DD];
    __shared__ float hid[DD];
    int b = blockIdx.x;
    int j = threadIdx.x;
    row[j] = te[b * DD + j];
    __syncthreads();
    float s = tb1[j];
    #pragma unroll 8
    for (int k = 0; k < DD; k++) s = fmaf(row[k], tw1[k * DD + j], s);
    hid[j] = silu_f(s);
    __syncthreads();
    float s2 = tb2[j];
    #pragma unroll 8
    for (int k = 0; k < DD; k++) s2 = fmaf(hid[k], tw2[k * DD + j], s2);
    g_tp[b * DD + j] = s2;
}

// ---------------- h = x + tp[batch] ----------------------------------------------
__global__ void init_h_kernel(const float* __restrict__ x, const void* __restrict__ batch) {
    int idx = blockIdx.x * blockDim.x + threadIdx.x;
    if (idx >= NN * DD) return;
    int n = idx >> 7;
    int d = idx & 127;
    long long bi = idx_at(batch, n);
    g_h[idx] = x[idx] + g_tp[(int)bi * DD + d];
}

// ---------------- zero kernels ----------------------------------------------------
__global__ void zero_deg_kernel() {
    int i = blockIdx.x * blockDim.x + threadIdx.x;
    if (i < NN) g_deg[i] = 0.f;
}
__global__ void zero_hacc_kernel() {
    int i = blockIdx.x * blockDim.x + threadIdx.x;
    if (i < NN * DD) g_Hacc[i] = 0.f;
}

// ---------------- edge prep: dist + degree ----------------------------------------
__global__ void prep_edges_kernel(const void* __restrict__ ei, const float* __restrict__ pos) {
    int e = blockIdx.x * blockDim.x + threadIdx.x;
    if (e >= EE) return;
    int r = (int)idx_at(ei, e);
    int c = (int)idx_at(ei, (long long)EE + e);
    float dx = pos[r * 3 + 0] - pos[c * 3 + 0];
    float dy = pos[r * 3 + 1] - pos[c * 3 + 1];
    float dz = pos[r * 3 + 2] - pos[c * 3 + 2];
    g_dist[e] = sqrtf(dx * dx + dy * dy + dz * dz);
    atomicAdd(&g_deg[c], 1.f);
}

__global__ void invdeg_kernel() {
    int i = blockIdx.x * blockDim.x + threadIdx.x;
    if (i < NN) g_invdeg[i] = 1.f / fmaxf(g_deg[i], 1.f);
}

// ---------------- edge message: hid = silu(P[col]+Q[row]+dist*w1c); scatter-add ---
__global__ void edge_msg_kernel(const void* __restrict__ ei, const float* __restrict__ w1c) {
    int t = blockIdx.x * blockDim.x + threadIdx.x;
    int e = t >> 5;
    int lane = t & 31;
    if (e >= EE) return;
    int r = (int)idx_at(ei, e);
    int c = (int)idx_at(ei, (long long)EE + e);
    float dist = g_dist[e];
    const float4 p = *(const float4*)(g_Z + (long long)c * 384 + lane * 4);
    const float4 q = *(const float4*)(g_Z + (long long)r * 384 + 128 + lane * 4);
    const float4 wc = *(const float4*)(w1c + lane * 4);
    float4 v;
    v.x = silu_f(p.x + q.x + dist * wc.x);
    v.y = silu_f(p.y + q.y + dist * wc.y);
    v.z = silu_f(p.z + q.z + dist * wc.z);
    v.w = silu_f(p.w + q.w + dist * wc.w);
    float* dst = g_Hacc + (long long)c * DD + lane * 4;
    asm volatile("red.global.add.v4.f32 [%0], {%1,%2,%3,%4};"
                 :: "l"(dst), "f"(v.x), "f"(v.y), "f"(v.z), "f"(v.w) : "memory");
}

// ---------------- Hacc *= invdeg ---------------------------------------------------
__global__ void scale_hacc_kernel() {
    int i = blockIdx.x * blockDim.x + threadIdx.x;
    if (i < NN * DD) g_Hacc[i] *= g_invdeg[i >> 7];
}

// ---------------- tiled SGEMM: C = [A0|A1] @ W + bias (+resid) (+silu tail) -------
// BM=128, BN=64, BK=32, 256 threads, thread tile 8x4
template<bool DUAL, bool RESID>
__global__ __launch_bounds__(256)
void gemm_kernel(const float* __restrict__ A0, int lda0,
                 const float* __restrict__ A1, int lda1,
                 const float* __restrict__ W,  const float* __restrict__ bias,
                 const float* __restrict__ resid, float* __restrict__ C, int ldc,
                 int nrows, int ncols, int Ktot, int silu_from) {
    __shared__ float As[32][132];  // [k][m], padded
    __shared__ float Ws[32][64];   // [k][n]
    const int tid = threadIdx.x;
    const int tcol = tid & 15;   // 0..15 -> 4 cols each
    const int trow = tid >> 4;   // 0..15 -> 8 rows each
    const int row0 = blockIdx.y * 128;
    const int col0 = blockIdx.x * 64;

    float acc[8][4];
    #pragma unroll
    for (int i = 0; i < 8; i++)
        #pragma unroll
        for (int j = 0; j < 4; j++) acc[i][j] = 0.f;

    for (int kt = 0; kt < Ktot; kt += 32) {
        // A tile: 128 rows x 32 k; 1024 float4 quads / 256 threads = 4 each
        #pragma unroll
        for (int it = 0; it < 4; ++it) {
            int idx = tid + it * 256;
            int m = idx >> 3;
            int k4 = (idx & 7) * 4;
            int grow = row0 + m;
            float4 v = make_float4(0.f, 0.f, 0.f, 0.f);
            if (grow < nrows) {
                int gk = kt + k4;
                const float* src;
                if (!DUAL || gk < 128) src = A0 + (long long)grow * lda0 + gk;
                else                   src = A1 + (long long)grow * lda1 + (gk - 128);
                v = *(const float4*)src;
            }
            As[k4 + 0][m] = v.x;
            As[k4 + 1][m] = v.y;
            As[k4 + 2][m] = v.z;
            As[k4 + 3][m] = v.w;
        }
        // W tile: 32 k x 64 n; 512 quads / 256 threads = 2 each
        #pragma unroll
        for (int it = 0; it < 2; ++it) {
            int idx = tid + it * 256;
            int k = idx >> 4;
            int j4 = (idx & 15) * 4;
            *(float4*)&Ws[k][j4] = *(const float4*)(W + (long long)(kt + k) * ncols + col0 + j4);
        }
        __syncthreads();
        #pragma unroll
        for (int k = 0; k < 32; ++k) {
            float a[8], w[4];
            *(float4*)&a[0] = *(const float4*)&As[k][trow * 8];
            *(float4*)&a[4] = *(const float4*)&As[k][trow * 8 + 4];
            *(float4*)&w[0] = *(const float4*)&Ws[k][tcol * 4];
            #pragma unroll
            for (int i = 0; i < 8; i++)
                #pragma unroll
                for (int j = 0; j < 4; j++)
                    acc[i][j] = fmaf(a[i], w[j], acc[i][j]);
        }
        __syncthreads();
    }

    #pragma unroll
    for (int i = 0; i < 8; i++) {
        int grow = row0 + trow * 8 + i;
        if (grow < nrows) {
            #pragma unroll
            for (int j = 0; j < 4; j++) {
                int gc = col0 + tcol * 4 + j;
                float v = acc[i][j] + bias[gc];
                if (gc >= silu_from) v = silu_f(v);
                if (RESID) v += resid[(long long)grow * ldc + gc];
                C[(long long)grow * ldc + gc] = v;
            }
        }
    }
}

// ---------------- layernorm: h = LN(hpre) ------------------------------------------
__global__ void ln_kernel(const float* __restrict__ gamma, const float* __restrict__ beta) {
    int gt = blockIdx.x * blockDim.x + threadIdx.x;
    int n = gt >> 5;
    int lane = gt & 31;
    if (n >= NN) return;
    float4 v = *(const float4*)(g_hpre + (long long)n * DD + lane * 4);
    float s = v.x + v.y + v.z + v.w;
    #pragma unroll
    for (int o = 16; o; o >>= 1) s += __shfl_xor_sync(0xffffffffu, s, o);
    float mean = s * (1.f / 128.f);
    float dx = v.x - mean, dy = v.y - mean, dz = v.z - mean, dw = v.w - mean;
    float sq = dx * dx + dy * dy + dz * dz + dw * dw;
    #pragma unroll
    for (int o = 16; o; o >>= 1) sq += __shfl_xor_sync(0xffffffffu, sq, o);
    float rs = rsqrtf(sq * (1.f / 128.f) + 1e-5f);
    float4 g4 = *(const float4*)(gamma + lane * 4);
    float4 b4 = *(const float4*)(beta + lane * 4);
    float4 o4;
    o4.x = dx * rs * g4.x + b4.x;
    o4.y = dy * rs * g4.y + b4.y;
    o4.z = dz * rs * g4.z + b4.z;
    o4.w = dw * rs * g4.w + b4.w;
    *(float4*)(g_h + (long long)n * DD + lane * 4) = o4;
}

// ---------------- final output: [h (N*D) | pos (N*3)] ------------------------------
__global__ void copy_out_kernel(const float* __restrict__ pos, float* __restrict__ out) {
    int i = blockIdx.x * blockDim.x + threadIdx.x;
    if (i < NN * DD) out[i] = g_h[i];
    if (i < NN * 3) out[NN * DD + i] = pos[i];
}

// ==================================================================================
extern "C" void kernel_launch(void* const* d_in, const int* in_sizes, int n_in,
                              void* d_out, int out_size) {
    const float* x        = (const float*)d_in[0];
    const float* pos      = (const float*)d_in[1];
    const float* time_emb = (const float*)d_in[2];
    const float* tw1      = (const float*)d_in[3];
    const float* tb1      = (const float*)d_in[4];
    const float* tw2      = (const float*)d_in[5];
    const float* tb2      = (const float*)d_in[6];
    const float* nw1      = (const float*)d_in[7];
    const float* nb1      = (const float*)d_in[8];
    const float* nw2      = (const float*)d_in[9];
    const float* nb2      = (const float*)d_in[10];
    const float* ew1      = (const float*)d_in[11];
    const float* eb1      = (const float*)d_in[12];
    const float* ew2      = (const float*)d_in[13];
    const float* eb2      = (const float*)d_in[14];
    const float* lng      = (const float*)d_in[15];
    const float* lnb      = (const float*)d_in[16];
    const void*  ei       = d_in[17];
    const void*  batch    = d_in[18];
    float* out = (float*)d_out;

    float *pH, *pHpre, *pZ, *pHacc, *pWk1, *pbk1, *pWk3, *pbk3;
    cudaGetSymbolAddress((void**)&pH,    g_h);
    cudaGetSymbolAddress((void**)&pHpre, g_hpre);
    cudaGetSymbolAddress((void**)&pZ,    g_Z);
    cudaGetSymbolAddress((void**)&pHacc, g_Hacc);
    cudaGetSymbolAddress((void**)&pWk1,  g_Wk1);
    cudaGetSymbolAddress((void**)&pbk1,  g_bk1);
    cudaGetSymbolAddress((void**)&pWk3,  g_Wk3);
    cudaGetSymbolAddress((void**)&pbk3,  g_bk3);

    detect_idx_kernel<<<1, 1>>>((const unsigned*)ei);
    pack_w_kernel<<<(LL * DD * 384 + 255) / 256, 256>>>(ew1, eb1, ew2, eb2, nw1, nb1, nw2, nb2);
    time_mlp_kernel<<<BB, DD>>>(time_emb, tw1, tb1, tw2, tb2);
    init_h_kernel<<<(NN * DD + 255) / 256, 256>>>(x, batch);
    zero_deg_kernel<<<(NN + 255) / 256, 256>>>();
    prep_edges_kernel<<<(EE + 255) / 256, 256>>>(ei, pos);
    invdeg_kernel<<<(NN + 255) / 256, 256>>>();

    const int rowTiles = (NN + 127) / 128;  // 391
    for (int l = 0; l < LL; l++) {
        // Z = [P | Q | silu(T)] = h @ [W1a | W1b | nw1] + [b1 | 0 | nb1]
        gemm_kernel<false, false><<<dim3(6, rowTiles), 256>>>(
            pH, DD, nullptr, 0,
            pWk1 + (long long)l * DD * 384, pbk1 + l * 384,
            nullptr, pZ, 384, NN, 384, 128, 256);

        zero_hacc_kernel<<<(NN * DD + 255) / 256, 256>>>();
        edge_msg_kernel<<<(EE * 32 + 255) / 256, 256>>>(ei, ew1 + (long long)l * 257 * 128 + 256 * 128);
        scale_hacc_kernel<<<(NN * DD + 255) / 256, 256>>>();

        // hpre = h + [T | Hacc/deg] @ [nw2 ; ew2] + (nb2 + eb2)
        gemm_kernel<true, true><<<dim3(2, rowTiles), 256>>>(
            pZ + 256, 384, pHacc, DD,
            pWk3 + (long long)l * 256 * DD, pbk3 + l * DD,
            pH, pHpre, DD, NN, DD, 256, 1 << 30);

        ln_kernel<<<(NN * 32 + 255) / 256, 256>>>(lng + l * DD, lnb + l * DD);
    }

    copy_out_kernel<<<(NN * DD + 255) / 256, 256>>>(pos, out);
}